// round 2
// baseline (speedup 1.0000x reference)
#include <cuda_runtime.h>
#include <math.h>

#define NN 50000
#define NE 800000
#define F  128
#define NEG_SLOPE 0.2f
#define EPSV 1e-10f

// ---------------- scratch (device globals; no allocation) ----------------
__device__ __align__(16) float d_Wh[NN * F];     // 25.6 MB
__device__ __align__(16) float d_Wt[F * F];      // W transposed
__device__ float d_s1[NN];
__device__ float d_s2[NN];
__device__ float d_expE[NE];
__device__ float d_sumExp[NN];
__device__ int   d_cnt[NN];
__device__ int   d_off[NN + 1];
__device__ int   d_cur[NN];
__device__ int   d_eidx[NE];
__device__ int   d_gmax;

__device__ __forceinline__ int f2oi(float f) {
    int i = __float_as_int(f);
    return i >= 0 ? i : i ^ 0x7FFFFFFF;
}
__device__ __forceinline__ float oi2f(int i) {
    return __int_as_float(i >= 0 ? i : i ^ 0x7FFFFFFF);
}

// ---------------- K0: init ----------------
__global__ void k0_init() {
    int i = blockIdx.x * blockDim.x + threadIdx.x;
    if (i < NN) { d_cnt[i] = 0; d_sumExp[i] = 0.f; }
    if (i == 0) d_gmax = f2oi(-3.0e38f);
}

// ---------------- transpose W -> d_Wt (d_Wt[k*F+j] = W[j*F+k]) ----------------
__global__ void k_transpose(const float* __restrict__ W) {
    __shared__ float t[32][33];
    int bx = blockIdx.x * 32, by = blockIdx.y * 32;
    t[threadIdx.y][threadIdx.x] = W[(by + threadIdx.y) * F + bx + threadIdx.x];
    __syncthreads();
    d_Wt[(bx + threadIdx.y) * F + by + threadIdx.x] = t[threadIdx.x][threadIdx.y];
}

// ---------------- K1: Wh = h @ W^T, fused s1 = Wh@a1, s2 = Wh@a2 ----------------
// 4 rows per warp; W^T staged in shared (64KB); lane owns 4 output features.
__global__ void k1_gemm(const float* __restrict__ h, const float* __restrict__ a) {
    extern __shared__ float Ws[];  // F*F floats; Ws[k*F + j] = W[j][k]
    for (int idx = threadIdx.x; idx < F * F; idx += blockDim.x) Ws[idx] = d_Wt[idx];
    __syncthreads();

    const int lane = threadIdx.x & 31;
    const int wid  = threadIdx.x >> 5;
    const int wpb  = blockDim.x >> 5;
    int q = blockIdx.x * wpb + wid;
    const int nq = NN / 4;  // 50000 % 4 == 0
    if (q >= nq) return;

    const float4* Ws4 = (const float4*)Ws;
    const float4* h4  = (const float4*)h;
    const float4* h40 = h4 + (size_t)q * 4 * 32;

    float4 acc0 = make_float4(0.f, 0.f, 0.f, 0.f);
    float4 acc1 = acc0, acc2 = acc0, acc3 = acc0;

#pragma unroll 4
    for (int k4 = 0; k4 < 32; k4++) {
        float4 hv0 = __ldg(h40 + k4);
        float4 hv1 = __ldg(h40 + 32 + k4);
        float4 hv2 = __ldg(h40 + 64 + k4);
        float4 hv3 = __ldg(h40 + 96 + k4);
#pragma unroll
        for (int kk = 0; kk < 4; kk++) {
            float4 wv = Ws4[(k4 * 4 + kk) * 32 + lane];
            float b0 = ((const float*)&hv0)[kk];
            float b1 = ((const float*)&hv1)[kk];
            float b2 = ((const float*)&hv2)[kk];
            float b3 = ((const float*)&hv3)[kk];
            acc0.x = fmaf(b0, wv.x, acc0.x); acc0.y = fmaf(b0, wv.y, acc0.y);
            acc0.z = fmaf(b0, wv.z, acc0.z); acc0.w = fmaf(b0, wv.w, acc0.w);
            acc1.x = fmaf(b1, wv.x, acc1.x); acc1.y = fmaf(b1, wv.y, acc1.y);
            acc1.z = fmaf(b1, wv.z, acc1.z); acc1.w = fmaf(b1, wv.w, acc1.w);
            acc2.x = fmaf(b2, wv.x, acc2.x); acc2.y = fmaf(b2, wv.y, acc2.y);
            acc2.z = fmaf(b2, wv.z, acc2.z); acc2.w = fmaf(b2, wv.w, acc2.w);
            acc3.x = fmaf(b3, wv.x, acc3.x); acc3.y = fmaf(b3, wv.y, acc3.y);
            acc3.z = fmaf(b3, wv.z, acc3.z); acc3.w = fmaf(b3, wv.w, acc3.w);
        }
    }

    int r0 = q * 4;
    float4* Wh4 = (float4*)d_Wh;
    Wh4[(size_t)(r0 + 0) * 32 + lane] = acc0;
    Wh4[(size_t)(r0 + 1) * 32 + lane] = acc1;
    Wh4[(size_t)(r0 + 2) * 32 + lane] = acc2;
    Wh4[(size_t)(r0 + 3) * 32 + lane] = acc3;

    float4 av1 = __ldg(&((const float4*)a)[lane]);        // a1
    float4 av2 = __ldg(&((const float4*)a)[32 + lane]);   // a2
    float p[8];
    p[0] = acc0.x*av1.x + acc0.y*av1.y + acc0.z*av1.z + acc0.w*av1.w;
    p[1] = acc1.x*av1.x + acc1.y*av1.y + acc1.z*av1.z + acc1.w*av1.w;
    p[2] = acc2.x*av1.x + acc2.y*av1.y + acc2.z*av1.z + acc2.w*av1.w;
    p[3] = acc3.x*av1.x + acc3.y*av1.y + acc3.z*av1.z + acc3.w*av1.w;
    p[4] = acc0.x*av2.x + acc0.y*av2.y + acc0.z*av2.z + acc0.w*av2.w;
    p[5] = acc1.x*av2.x + acc1.y*av2.y + acc1.z*av2.z + acc1.w*av2.w;
    p[6] = acc2.x*av2.x + acc2.y*av2.y + acc2.z*av2.z + acc2.w*av2.w;
    p[7] = acc3.x*av2.x + acc3.y*av2.y + acc3.z*av2.z + acc3.w*av2.w;
#pragma unroll
    for (int d = 16; d; d >>= 1) {
#pragma unroll
        for (int t = 0; t < 8; t++) p[t] += __shfl_xor_sync(0xffffffffu, p[t], d);
    }
    if (lane == 0) {
        d_s1[r0 + 0] = p[0]; d_s1[r0 + 1] = p[1]; d_s1[r0 + 2] = p[2]; d_s1[r0 + 3] = p[3];
        d_s2[r0 + 0] = p[4]; d_s2[r0 + 1] = p[5]; d_s2[r0 + 2] = p[6]; d_s2[r0 + 3] = p[7];
    }
}

// ---------------- K2: global max of e, and per-row edge counts ----------------
__global__ void k2_max_count(const int* __restrict__ rows, const int* __restrict__ cols) {
    int i = blockIdx.x * blockDim.x + threadIdx.x;
    float lmax = -3.0e38f;
    if (i < NE) {
        int r = rows[i], c = cols[i];
        float s = d_s1[r] + d_s2[c];
        float e = s > 0.f ? s : NEG_SLOPE * s;
        lmax = e;
        atomicAdd(&d_cnt[r], 1);
    }
#pragma unroll
    for (int d = 16; d; d >>= 1) lmax = fmaxf(lmax, __shfl_xor_sync(0xffffffffu, lmax, d));
    __shared__ float smax[32];
    int lane = threadIdx.x & 31, wid = threadIdx.x >> 5;
    if (lane == 0) smax[wid] = lmax;
    __syncthreads();
    if (wid == 0) {
        int nw = blockDim.x >> 5;
        float v = lane < nw ? smax[lane] : -3.0e38f;
#pragma unroll
        for (int d = 16; d; d >>= 1) v = fmaxf(v, __shfl_xor_sync(0xffffffffu, v, d));
        if (lane == 0) atomicMax(&d_gmax, f2oi(v));
    }
}

// ---------------- K3: exclusive scan of counts (single block, 1024 threads) ----------------
#define SCAN_CHUNK 49  // ceil(50000/1024)
__global__ void k3_scan() {
    int tid = threadIdx.x, lane = tid & 31, wid = tid >> 5;
    int start = tid * SCAN_CHUNK;
    int end = start + SCAN_CHUNK; if (end > NN) end = NN;
    int sum = 0;
    for (int i = start; i < end; i++) sum += d_cnt[i];

    int incl = sum;
#pragma unroll
    for (int d = 1; d < 32; d <<= 1) {
        int t = __shfl_up_sync(0xffffffffu, incl, d);
        if (lane >= d) incl += t;
    }
    __shared__ int wsum[32];
    if (lane == 31) wsum[wid] = incl;
    __syncthreads();
    if (wid == 0) {
        int wv = wsum[lane];
        int wincl = wv;
#pragma unroll
        for (int d = 1; d < 32; d <<= 1) {
            int t = __shfl_up_sync(0xffffffffu, wincl, d);
            if (lane >= d) wincl += t;
        }
        wsum[lane] = wincl - wv;  // exclusive warp offset
    }
    __syncthreads();
    int excl = wsum[wid] + incl - sum;

    int run = excl;
    for (int i = start; i < end; i++) {
        int c = d_cnt[i];
        d_off[i] = run;
        d_cur[i] = run;
        run += c;
    }
    if (tid == 1023) d_off[NN] = run;  // last thread has run == total
}

// ---------------- K4: exp(e - max), sumExp, CSR scatter ----------------
__global__ void k4_exp_scatter(const int* __restrict__ rows, const int* __restrict__ cols) {
    int i = blockIdx.x * blockDim.x + threadIdx.x;
    if (i >= NE) return;
    float gmax = oi2f(d_gmax);
    int r = rows[i], c = cols[i];
    float s = d_s1[r] + d_s2[c];
    float e = s > 0.f ? s : NEG_SLOPE * s;
    float ex = __expf(e - gmax);
    d_expE[i] = ex;
    atomicAdd(&d_sumExp[r], ex);
    int pos = atomicAdd(&d_cur[r], 1);
    d_eidx[pos] = i;
}

// ---------------- K5: per-row aggregation + elu (one warp per row) ----------------
__global__ void k5_agg(const int* __restrict__ cols, float* __restrict__ out) {
    int r    = blockIdx.x * (blockDim.x >> 5) + (threadIdx.x >> 5);
    int lane = threadIdx.x & 31;
    if (r >= NN) return;
    int s = d_off[r], e = d_off[r + 1];
    float inv = 1.f / (d_sumExp[r] + EPSV);
    float4 acc = make_float4(0.f, 0.f, 0.f, 0.f);
    const float4* Wh4 = (const float4*)d_Wh;

    int j = s;
    for (; j + 1 < e; j += 2) {
        int i0 = d_eidx[j], i1 = d_eidx[j + 1];
        int c0 = __ldg(&cols[i0]), c1 = __ldg(&cols[i1]);
        float a0 = d_expE[i0] * inv;
        float a1 = d_expE[i1] * inv;
        float4 w0 = Wh4[(size_t)c0 * 32 + lane];
        float4 w1 = Wh4[(size_t)c1 * 32 + lane];
        acc.x = fmaf(a0, w0.x, acc.x); acc.y = fmaf(a0, w0.y, acc.y);
        acc.z = fmaf(a0, w0.z, acc.z); acc.w = fmaf(a0, w0.w, acc.w);
        acc.x = fmaf(a1, w1.x, acc.x); acc.y = fmaf(a1, w1.y, acc.y);
        acc.z = fmaf(a1, w1.z, acc.z); acc.w = fmaf(a1, w1.w, acc.w);
    }
    if (j < e) {
        int i0 = d_eidx[j];
        int c0 = __ldg(&cols[i0]);
        float a0 = d_expE[i0] * inv;
        float4 w0 = Wh4[(size_t)c0 * 32 + lane];
        acc.x = fmaf(a0, w0.x, acc.x); acc.y = fmaf(a0, w0.y, acc.y);
        acc.z = fmaf(a0, w0.z, acc.z); acc.w = fmaf(a0, w0.w, acc.w);
    }
    // elu
    acc.x = acc.x > 0.f ? acc.x : expm1f(acc.x);
    acc.y = acc.y > 0.f ? acc.y : expm1f(acc.y);
    acc.z = acc.z > 0.f ? acc.z : expm1f(acc.z);
    acc.w = acc.w > 0.f ? acc.w : expm1f(acc.w);
    ((float4*)out)[(size_t)r * 32 + lane] = acc;
}

// ---------------- launch ----------------
extern "C" void kernel_launch(void* const* d_in, const int* in_sizes, int n_in,
                              void* d_out, int out_size) {
    const float* h  = (const float*)d_in[0];
    const int*   ei = (const int*)d_in[1];
    const float* W  = (const float*)d_in[2];
    const float* a  = (const float*)d_in[3];
    const int* rows = ei;
    const int* cols = ei + NE;
    float* out = (float*)d_out;

    cudaFuncSetAttribute(k1_gemm, cudaFuncAttributeMaxDynamicSharedMemorySize, F * F * 4);

    k0_init<<<(NN + 255) / 256, 256>>>();
    k_transpose<<<dim3(4, 4), dim3(32, 32)>>>(W);
    k1_gemm<<<(NN / 4 + 7) / 8, 256, F * F * 4>>>(h, a);
    k2_max_count<<<(NE + 255) / 256, 256>>>(rows, cols);
    k3_scan<<<1, 1024>>>();
    k4_exp_scatter<<<(NE + 255) / 256, 256>>>(rows, cols);
    k5_agg<<<(NN + 7) / 8, 256>>>(cols, out);
}

// round 3
// speedup vs baseline: 1.2295x; 1.2295x over previous
#include <cuda_runtime.h>
#include <math.h>

#define NN 50000
#define NE 800000
#define F  128
#define NEG_SLOPE 0.2f
#define EPSV 1e-10f

// ---------------- scratch (device globals; no allocation) ----------------
__device__ __align__(16) float d_Wh[NN * F];     // 25.6 MB
__device__ __align__(16) float d_Wt[F * F];      // W transposed
__device__ float d_s1[NN];
__device__ float d_s2[NN];
__device__ float d_expE[NE];
__device__ int   d_rank[NE];
__device__ float d_sumExp[NN];
__device__ int   d_cnt[NN];
__device__ int   d_off[NN + 1];
__device__ __align__(8) int2 d_epack[NE];        // (col, exp bits) in CSR order

// ---------------- K0: init ----------------
__global__ void k0_init() {
    int i = blockIdx.x * blockDim.x + threadIdx.x;
    if (i < NN) { d_cnt[i] = 0; d_sumExp[i] = 0.f; }
}

// ---------------- transpose W -> d_Wt (d_Wt[k*F+j] = W[j*F+k]) ----------------
__global__ void k_transpose(const float* __restrict__ W) {
    __shared__ float t[32][33];
    int bx = blockIdx.x * 32, by = blockIdx.y * 32;
    t[threadIdx.y][threadIdx.x] = W[(by + threadIdx.y) * F + bx + threadIdx.x];
    __syncthreads();
    d_Wt[(bx + threadIdx.y) * F + by + threadIdx.x] = t[threadIdx.x][threadIdx.y];
}

// ---------------- K1: Wh = h @ W^T, fused s1 = Wh@a1, s2 = Wh@a2 ----------------
// 4 rows per warp; W^T staged in shared (64KB); lane owns 4 output features.
__global__ void k1_gemm(const float* __restrict__ h, const float* __restrict__ a) {
    extern __shared__ float Ws[];  // F*F floats; Ws[k*F + j] = W[j][k]
    for (int idx = threadIdx.x; idx < F * F; idx += blockDim.x) Ws[idx] = d_Wt[idx];
    __syncthreads();

    const int lane = threadIdx.x & 31;
    const int wid  = threadIdx.x >> 5;
    const int wpb  = blockDim.x >> 5;
    int q = blockIdx.x * wpb + wid;
    const int nq = NN / 4;  // 50000 % 4 == 0
    if (q >= nq) return;

    const float4* Ws4 = (const float4*)Ws;
    const float4* h4  = (const float4*)h;
    const float4* h40 = h4 + (size_t)q * 4 * 32;

    float4 acc0 = make_float4(0.f, 0.f, 0.f, 0.f);
    float4 acc1 = acc0, acc2 = acc0, acc3 = acc0;

#pragma unroll 4
    for (int k4 = 0; k4 < 32; k4++) {
        float4 hv0 = __ldg(h40 + k4);
        float4 hv1 = __ldg(h40 + 32 + k4);
        float4 hv2 = __ldg(h40 + 64 + k4);
        float4 hv3 = __ldg(h40 + 96 + k4);
#pragma unroll
        for (int kk = 0; kk < 4; kk++) {
            float4 wv = Ws4[(k4 * 4 + kk) * 32 + lane];
            float b0 = ((const float*)&hv0)[kk];
            float b1 = ((const float*)&hv1)[kk];
            float b2 = ((const float*)&hv2)[kk];
            float b3 = ((const float*)&hv3)[kk];
            acc0.x = fmaf(b0, wv.x, acc0.x); acc0.y = fmaf(b0, wv.y, acc0.y);
            acc0.z = fmaf(b0, wv.z, acc0.z); acc0.w = fmaf(b0, wv.w, acc0.w);
            acc1.x = fmaf(b1, wv.x, acc1.x); acc1.y = fmaf(b1, wv.y, acc1.y);
            acc1.z = fmaf(b1, wv.z, acc1.z); acc1.w = fmaf(b1, wv.w, acc1.w);
            acc2.x = fmaf(b2, wv.x, acc2.x); acc2.y = fmaf(b2, wv.y, acc2.y);
            acc2.z = fmaf(b2, wv.z, acc2.z); acc2.w = fmaf(b2, wv.w, acc2.w);
            acc3.x = fmaf(b3, wv.x, acc3.x); acc3.y = fmaf(b3, wv.y, acc3.y);
            acc3.z = fmaf(b3, wv.z, acc3.z); acc3.w = fmaf(b3, wv.w, acc3.w);
        }
    }

    int r0 = q * 4;
    float4* Wh4 = (float4*)d_Wh;
    Wh4[(size_t)(r0 + 0) * 32 + lane] = acc0;
    Wh4[(size_t)(r0 + 1) * 32 + lane] = acc1;
    Wh4[(size_t)(r0 + 2) * 32 + lane] = acc2;
    Wh4[(size_t)(r0 + 3) * 32 + lane] = acc3;

    float4 av1 = __ldg(&((const float4*)a)[lane]);        // a1
    float4 av2 = __ldg(&((const float4*)a)[32 + lane]);   // a2
    float p[8];
    p[0] = acc0.x*av1.x + acc0.y*av1.y + acc0.z*av1.z + acc0.w*av1.w;
    p[1] = acc1.x*av1.x + acc1.y*av1.y + acc1.z*av1.z + acc1.w*av1.w;
    p[2] = acc2.x*av1.x + acc2.y*av1.y + acc2.z*av1.z + acc2.w*av1.w;
    p[3] = acc3.x*av1.x + acc3.y*av1.y + acc3.z*av1.z + acc3.w*av1.w;
    p[4] = acc0.x*av2.x + acc0.y*av2.y + acc0.z*av2.z + acc0.w*av2.w;
    p[5] = acc1.x*av2.x + acc1.y*av2.y + acc1.z*av2.z + acc1.w*av2.w;
    p[6] = acc2.x*av2.x + acc2.y*av2.y + acc2.z*av2.z + acc2.w*av2.w;
    p[7] = acc3.x*av2.x + acc3.y*av2.y + acc3.z*av2.z + acc3.w*av2.w;
#pragma unroll
    for (int d = 16; d; d >>= 1) {
#pragma unroll
        for (int t = 0; t < 8; t++) p[t] += __shfl_xor_sync(0xffffffffu, p[t], d);
    }
    if (lane == 0) {
        d_s1[r0 + 0] = p[0]; d_s1[r0 + 1] = p[1]; d_s1[r0 + 2] = p[2]; d_s1[r0 + 3] = p[3];
        d_s2[r0 + 0] = p[4]; d_s2[r0 + 1] = p[5]; d_s2[r0 + 2] = p[6]; d_s2[r0 + 3] = p[7];
    }
}

// ---------------- K2: per-edge exp (no max needed: softmax shift-invariant),
//                  per-row counts (atomic returns rank), per-row sumExp ----------------
__global__ void k2_exp_count(const int* __restrict__ rows, const int* __restrict__ cols) {
    int i = blockIdx.x * blockDim.x + threadIdx.x;
    if (i >= NE) return;
    int r = __ldg(&rows[i]), c = __ldg(&cols[i]);
    float s = d_s1[r] + d_s2[c];
    float e = s > 0.f ? s : NEG_SLOPE * s;
    float ex = __expf(e);
    d_expE[i] = ex;
    int rank = atomicAdd(&d_cnt[r], 1);
    d_rank[i] = rank;
    atomicAdd(&d_sumExp[r], ex);
}

// ---------------- K3: exclusive scan of counts (single block, 1024 threads) ----------------
#define SCAN_CHUNK 49  // ceil(50000/1024)
__global__ void k3_scan() {
    int tid = threadIdx.x, lane = tid & 31, wid = tid >> 5;
    int start = tid * SCAN_CHUNK;
    int end = start + SCAN_CHUNK; if (end > NN) end = NN;
    int sum = 0;
    for (int i = start; i < end; i++) sum += d_cnt[i];

    int incl = sum;
#pragma unroll
    for (int d = 1; d < 32; d <<= 1) {
        int t = __shfl_up_sync(0xffffffffu, incl, d);
        if (lane >= d) incl += t;
    }
    __shared__ int wsum[32];
    if (lane == 31) wsum[wid] = incl;
    __syncthreads();
    if (wid == 0) {
        int wv = wsum[lane];
        int wincl = wv;
#pragma unroll
        for (int d = 1; d < 32; d <<= 1) {
            int t = __shfl_up_sync(0xffffffffu, wincl, d);
            if (lane >= d) wincl += t;
        }
        wsum[lane] = wincl - wv;  // exclusive warp offset
    }
    __syncthreads();
    int excl = wsum[wid] + incl - sum;

    int run = excl;
    for (int i = start; i < end; i++) {
        int c = d_cnt[i];
        d_off[i] = run;
        run += c;
    }
    if (tid == 1023) d_off[NN] = run;
}

// ---------------- K4: pure scatter into CSR order (no atomics) ----------------
__global__ void k4_scatter(const int* __restrict__ rows, const int* __restrict__ cols) {
    int i = blockIdx.x * blockDim.x + threadIdx.x;
    if (i >= NE) return;
    int r = __ldg(&rows[i]);
    int pos = d_off[r] + d_rank[i];
    int2 p;
    p.x = __ldg(&cols[i]);
    p.y = __float_as_int(d_expE[i]);
    d_epack[pos] = p;
}

// ---------------- K5: per-row aggregation + elu (one warp per row) ----------------
__global__ void k5_agg(float* __restrict__ out) {
    int r    = blockIdx.x * (blockDim.x >> 5) + (threadIdx.x >> 5);
    int lane = threadIdx.x & 31;
    if (r >= NN) return;
    int s = d_off[r], e = d_off[r + 1];
    float4 acc = make_float4(0.f, 0.f, 0.f, 0.f);
    const float4* Wh4 = (const float4*)d_Wh;

    int j = s;
    for (; j + 1 < e; j += 2) {
        int2 p0 = d_epack[j];
        int2 p1 = d_epack[j + 1];
        float a0 = __int_as_float(p0.y);
        float a1 = __int_as_float(p1.y);
        float4 w0 = Wh4[(size_t)p0.x * 32 + lane];
        float4 w1 = Wh4[(size_t)p1.x * 32 + lane];
        acc.x = fmaf(a0, w0.x, acc.x); acc.y = fmaf(a0, w0.y, acc.y);
        acc.z = fmaf(a0, w0.z, acc.z); acc.w = fmaf(a0, w0.w, acc.w);
        acc.x = fmaf(a1, w1.x, acc.x); acc.y = fmaf(a1, w1.y, acc.y);
        acc.z = fmaf(a1, w1.z, acc.z); acc.w = fmaf(a1, w1.w, acc.w);
    }
    if (j < e) {
        int2 p0 = d_epack[j];
        float a0 = __int_as_float(p0.y);
        float4 w0 = Wh4[(size_t)p0.x * 32 + lane];
        acc.x = fmaf(a0, w0.x, acc.x); acc.y = fmaf(a0, w0.y, acc.y);
        acc.z = fmaf(a0, w0.z, acc.z); acc.w = fmaf(a0, w0.w, acc.w);
    }
    // normalize once at the end: alpha_j = exp_j * inv
    float inv = 1.f / (d_sumExp[r] + EPSV);
    acc.x *= inv; acc.y *= inv; acc.z *= inv; acc.w *= inv;
    // elu
    acc.x = acc.x > 0.f ? acc.x : expm1f(acc.x);
    acc.y = acc.y > 0.f ? acc.y : expm1f(acc.y);
    acc.z = acc.z > 0.f ? acc.z : expm1f(acc.z);
    acc.w = acc.w > 0.f ? acc.w : expm1f(acc.w);
    ((float4*)out)[(size_t)r * 32 + lane] = acc;
}

// ---------------- launch ----------------
extern "C" void kernel_launch(void* const* d_in, const int* in_sizes, int n_in,
                              void* d_out, int out_size) {
    const float* h  = (const float*)d_in[0];
    const int*   ei = (const int*)d_in[1];
    const float* W  = (const float*)d_in[2];
    const float* a  = (const float*)d_in[3];
    const int* rows = ei;
    const int* cols = ei + NE;
    float* out = (float*)d_out;

    cudaFuncSetAttribute(k1_gemm, cudaFuncAttributeMaxDynamicSharedMemorySize, F * F * 4);

    k0_init<<<(NN + 255) / 256, 256>>>();
    k_transpose<<<dim3(4, 4), dim3(32, 32)>>>(W);
    k1_gemm<<<(NN / 4 + 7) / 8, 256, F * F * 4>>>(h, a);
    k2_exp_count<<<(NE + 255) / 256, 256>>>(rows, cols);
    k3_scan<<<1, 1024>>>();
    k4_scatter<<<(NE + 255) / 256, 256>>>(rows, cols);
    k5_agg<<<(NN + 7) / 8, 256>>>(out);
}

// round 8
// speedup vs baseline: 1.4580x; 1.1858x over previous
#include <cuda_runtime.h>
#include <math.h>

#define NN 50000
#define NE 800000
#define F  128
#define NEG_SLOPE 0.2f
#define EPSV 1e-10f

#define NBLK3 49   // ceil(50000/1024)

// ---------------- scratch (device globals; no allocation) ----------------
__device__ __align__(16) float d_Wh[NN * F];     // 25.6 MB
__device__ float d_s1[NN];
__device__ float d_s2[NN];
__device__ __align__(8) int2 d_re[NE];           // (rank, exp bits) per edge
__device__ int   d_cnt[NN];                      // zero-initialized; left zeroed by k3a
__device__ int   d_off[NN + 1];
__device__ int   d_bsum[NBLK3];
__device__ int   d_bpre[NBLK3];
__device__ __align__(8) int2 d_epack[NE];        // (col, exp bits) in CSR order

// ---------------- K1: Wh = h @ W^T, fused s1 = Wh@a1, s2 = Wh@a2 ----------------
// W transposed into padded shared (stride 132 floats -> conflict-free LDS.128).
// 4 rows per warp; lane owns 4 output features.
__global__ void k1_gemm(const float* __restrict__ h, const float* __restrict__ W,
                        const float* __restrict__ a) {
    extern __shared__ float Ws[];  // 128 * 132 floats; Ws[k*132 + j] = W[j*F + k]
    for (int idx = threadIdx.x; idx < F * F; idx += blockDim.x) {
        int j = idx >> 7;      // output feature (row of W)
        int k = idx & 127;     // input feature
        Ws[k * 132 + j] = W[idx];
    }
    __syncthreads();

    const int lane = threadIdx.x & 31;
    const int wid  = threadIdx.x >> 5;
    const int wpb  = blockDim.x >> 5;
    int q = blockIdx.x * wpb + wid;
    const int nq = NN / 4;  // 12500
    if (q >= nq) return;

    const float4* Ws4 = (const float4*)Ws;   // row stride 33 float4
    const float4* h40 = ((const float4*)h) + (size_t)q * 4 * 32;

    float4 acc0 = make_float4(0.f, 0.f, 0.f, 0.f);
    float4 acc1 = acc0, acc2 = acc0, acc3 = acc0;

#pragma unroll 4
    for (int k4 = 0; k4 < 32; k4++) {
        float4 hv0 = __ldg(h40 + k4);
        float4 hv1 = __ldg(h40 + 32 + k4);
        float4 hv2 = __ldg(h40 + 64 + k4);
        float4 hv3 = __ldg(h40 + 96 + k4);
#pragma unroll
        for (int kk = 0; kk < 4; kk++) {
            float4 wv = Ws4[(k4 * 4 + kk) * 33 + lane];
            float b0 = ((const float*)&hv0)[kk];
            float b1 = ((const float*)&hv1)[kk];
            float b2 = ((const float*)&hv2)[kk];
            float b3 = ((const float*)&hv3)[kk];
            acc0.x = fmaf(b0, wv.x, acc0.x); acc0.y = fmaf(b0, wv.y, acc0.y);
            acc0.z = fmaf(b0, wv.z, acc0.z); acc0.w = fmaf(b0, wv.w, acc0.w);
            acc1.x = fmaf(b1, wv.x, acc1.x); acc1.y = fmaf(b1, wv.y, acc1.y);
            acc1.z = fmaf(b1, wv.z, acc1.z); acc1.w = fmaf(b1, wv.w, acc1.w);
            acc2.x = fmaf(b2, wv.x, acc2.x); acc2.y = fmaf(b2, wv.y, acc2.y);
            acc2.z = fmaf(b2, wv.z, acc2.z); acc2.w = fmaf(b2, wv.w, acc2.w);
            acc3.x = fmaf(b3, wv.x, acc3.x); acc3.y = fmaf(b3, wv.y, acc3.y);
            acc3.z = fmaf(b3, wv.z, acc3.z); acc3.w = fmaf(b3, wv.w, acc3.w);
        }
    }

    int r0 = q * 4;
    float4* Wh4 = (float4*)d_Wh;
    Wh4[(size_t)(r0 + 0) * 32 + lane] = acc0;
    Wh4[(size_t)(r0 + 1) * 32 + lane] = acc1;
    Wh4[(size_t)(r0 + 2) * 32 + lane] = acc2;
    Wh4[(size_t)(r0 + 3) * 32 + lane] = acc3;

    float4 av1 = __ldg(&((const float4*)a)[lane]);        // a1
    float4 av2 = __ldg(&((const float4*)a)[32 + lane]);   // a2
    float p[8];
    p[0] = acc0.x*av1.x + acc0.y*av1.y + acc0.z*av1.z + acc0.w*av1.w;
    p[1] = acc1.x*av1.x + acc1.y*av1.y + acc1.z*av1.z + acc1.w*av1.w;
    p[2] = acc2.x*av1.x + acc2.y*av1.y + acc2.z*av1.z + acc2.w*av1.w;
    p[3] = acc3.x*av1.x + acc3.y*av1.y + acc3.z*av1.z + acc3.w*av1.w;
    p[4] = acc0.x*av2.x + acc0.y*av2.y + acc0.z*av2.z + acc0.w*av2.w;
    p[5] = acc1.x*av2.x + acc1.y*av2.y + acc1.z*av2.z + acc1.w*av2.w;
    p[6] = acc2.x*av2.x + acc2.y*av2.y + acc2.z*av2.z + acc2.w*av2.w;
    p[7] = acc3.x*av2.x + acc3.y*av2.y + acc3.z*av2.z + acc3.w*av2.w;
#pragma unroll
    for (int d = 16; d; d >>= 1) {
#pragma unroll
        for (int t = 0; t < 8; t++) p[t] += __shfl_xor_sync(0xffffffffu, p[t], d);
    }
    if (lane == 0) {
        d_s1[r0 + 0] = p[0]; d_s1[r0 + 1] = p[1]; d_s1[r0 + 2] = p[2]; d_s1[r0 + 3] = p[3];
        d_s2[r0 + 0] = p[4]; d_s2[r0 + 1] = p[5]; d_s2[r0 + 2] = p[6]; d_s2[r0 + 3] = p[7];
    }
}

// ---------------- K2: per-edge exp (softmax shift-invariant -> no max),
//                  rank within row via single atomic; pack (rank, exp) ----------------
__global__ void k2_exp_count(const int* __restrict__ rows, const int* __restrict__ cols) {
    int i = blockIdx.x * blockDim.x + threadIdx.x;
    if (i >= NE) return;
    int r = __ldg(&rows[i]), c = __ldg(&cols[i]);
    float s = d_s1[r] + d_s2[c];
    float e = s > 0.f ? s : NEG_SLOPE * s;
    float ex = __expf(e);
    int rank = atomicAdd(&d_cnt[r], 1);
    int2 p; p.x = rank; p.y = __float_as_int(ex);
    d_re[i] = p;
}

// ---------------- K3a: block-level exclusive scan of counts; zero cnt ----------------
__global__ void k3a_scan() {
    int tid = threadIdx.x, lane = tid & 31, wid = tid >> 5;
    int i = blockIdx.x * 1024 + tid;
    int v = (i < NN) ? d_cnt[i] : 0;
    if (i < NN) d_cnt[i] = 0;   // restore invariant for next replay

    int incl = v;
#pragma unroll
    for (int d = 1; d < 32; d <<= 1) {
        int t = __shfl_up_sync(0xffffffffu, incl, d);
        if (lane >= d) incl += t;
    }
    __shared__ int ws[32];
    if (lane == 31) ws[wid] = incl;
    __syncthreads();
    if (wid == 0) {
        int wv = ws[lane];
        int wincl = wv;
#pragma unroll
        for (int d = 1; d < 32; d <<= 1) {
            int t = __shfl_up_sync(0xffffffffu, wincl, d);
            if (lane >= d) wincl += t;
        }
        ws[lane] = wincl - wv;  // exclusive warp offsets
    }
    __syncthreads();
    int excl = ws[wid] + incl - v;
    if (i <= NN) d_off[i] = excl;
    if (tid == 1023) d_bsum[blockIdx.x] = excl + v;  // block total
}

// ---------------- K3b: scan of 49 block sums (one block, 64 threads) ----------------
__global__ void k3b_scan() {
    int t = threadIdx.x, lane = t & 31, w = t >> 5;
    int v = (t < NBLK3) ? d_bsum[t] : 0;
    int incl = v;
#pragma unroll
    for (int d = 1; d < 32; d <<= 1) {
        int x = __shfl_up_sync(0xffffffffu, incl, d);
        if (lane >= d) incl += x;
    }
    __shared__ int s0;
    if (t == 31) s0 = incl;
    __syncthreads();
    int excl = incl - v + (w ? s0 : 0);
    if (t < NBLK3) d_bpre[t] = excl;
}

// ---------------- K3c: add block offsets ----------------
__global__ void k3c_add() {
    int i = blockIdx.x * blockDim.x + threadIdx.x;
    if (i <= NN) d_off[i] += d_bpre[i >> 10];
}

// ---------------- K4: pure scatter into CSR order (no atomics) ----------------
__global__ void k4_scatter(const int* __restrict__ rows, const int* __restrict__ cols) {
    int i = blockIdx.x * blockDim.x + threadIdx.x;
    if (i >= NE) return;
    int r = __ldg(&rows[i]);
    int2 q = d_re[i];
    int pos = d_off[r] + q.x;
    int2 p; p.x = __ldg(&cols[i]); p.y = q.y;
    d_epack[pos] = p;
}

// ---------------- K5: per-row aggregation + softmax normalize + elu ----------------
// One warp per row. Coalesced chunk load of epack, shuffle-distributed addresses
// -> all Wh gathers in a chunk are independent (MLP ~= degree).
__global__ void k5_agg(float* __restrict__ out) {
    int r    = blockIdx.x * (blockDim.x >> 5) + (threadIdx.x >> 5);
    int lane = threadIdx.x & 31;
    if (r >= NN) return;
    int s = d_off[r], e = d_off[r + 1];
    float4 acc = make_float4(0.f, 0.f, 0.f, 0.f);
    float sum = 0.f;
    const float4* Wh4 = (const float4*)d_Wh;

    for (int base = s; base < e; base += 32) {
        int n = e - base; if (n > 32) n = 32;
        int2 p = make_int2(0, 0);
        if (lane < n) p = d_epack[base + lane];
#pragma unroll 4
        for (int t = 0; t < n; t++) {
            int   c  = __shfl_sync(0xffffffffu, p.x, t);
            float av = __int_as_float(__shfl_sync(0xffffffffu, p.y, t));
            sum += av;
            float4 w = Wh4[(size_t)c * 32 + lane];
            acc.x = fmaf(av, w.x, acc.x); acc.y = fmaf(av, w.y, acc.y);
            acc.z = fmaf(av, w.z, acc.z); acc.w = fmaf(av, w.w, acc.w);
        }
    }

    float inv = 1.f / (sum + EPSV);
    acc.x *= inv; acc.y *= inv; acc.z *= inv; acc.w *= inv;
    acc.x = acc.x > 0.f ? acc.x : expm1f(acc.x);
    acc.y = acc.y > 0.f ? acc.y : expm1f(acc.y);
    acc.z = acc.z > 0.f ? acc.z : expm1f(acc.z);
    acc.w = acc.w > 0.f ? acc.w : expm1f(acc.w);
    ((float4*)out)[(size_t)r * 32 + lane] = acc;
}

// ---------------- launch ----------------
extern "C" void kernel_launch(void* const* d_in, const int* in_sizes, int n_in,
                              void* d_out, int out_size) {
    const float* h  = (const float*)d_in[0];
    const int*   ei = (const int*)d_in[1];
    const float* W  = (const float*)d_in[2];
    const float* a  = (const float*)d_in[3];
    const int* rows = ei;
    const int* cols = ei + NE;
    float* out = (float*)d_out;

    cudaFuncSetAttribute(k1_gemm, cudaFuncAttributeMaxDynamicSharedMemorySize, 128 * 132 * 4);

    k1_gemm<<<(NN / 4 + 7) / 8, 256, 128 * 132 * 4>>>(h, W, a);
    k2_exp_count<<<(NE + 255) / 256, 256>>>(rows, cols);
    k3a_scan<<<NBLK3, 1024>>>();
    k3b_scan<<<1, 64>>>();
    k3c_add<<<(NN + 256) / 256, 256>>>();
    k4_scatter<<<(NE + 255) / 256, 256>>>(rows, cols);
    k5_agg<<<(NN + 7) / 8, 256>>>(out);
}

// round 9
// speedup vs baseline: 1.6733x; 1.1477x over previous
#include <cuda_runtime.h>
#include <math.h>

#define NN 50000
#define NE 800000
#define F  128
#define NEG_SLOPE 0.2f
#define EPSV 1e-10f

#define NBLK3 49   // ceil(50000/1024)

// ---------------- scratch (device globals; no allocation) ----------------
__device__ __align__(16) float d_Wh[NN * F];     // 25.6 MB
__device__ float d_s1[NN];
__device__ float d_s2[NN];
__device__ int   d_rank[NE];                     // rank of edge within its row
__device__ int   d_cnt[NN];                      // zero-initialized; re-zeroed by k3a
__device__ int   d_off[NN + 1];
__device__ int   d_bsum[NBLK3];
__device__ int   d_bpre[NBLK3];
__device__ int   d_ecol[NE];                     // cols in CSR order

// ---------------- packed f32x2 helpers (sm_103a) ----------------
__device__ __forceinline__ void fma2(unsigned long long& d, unsigned long long a,
                                     unsigned long long b) {
    asm("fma.rn.f32x2 %0, %1, %2, %0;" : "+l"(d) : "l"(a), "l"(b));
}
__device__ __forceinline__ unsigned long long pack2(float x) {
    unsigned long long r;
    asm("mov.b64 %0, {%1, %1};" : "=l"(r) : "f"(x));
    return r;
}
__device__ __forceinline__ float2 unpack2(unsigned long long v) {
    float lo, hi;
    asm("mov.b64 {%0, %1}, %2;" : "=f"(lo), "=f"(hi) : "l"(v));
    return make_float2(lo, hi);
}

// ---------------- K1: Wh = h @ W^T (packed f32x2), fused s1/s2 ----------------
// W transposed into padded shared (stride 132 floats / 33 float4 -> conflict-free).
// 4 rows per warp; lane owns 4 output features (2 packed pairs).
__global__ void k1_gemm(const float* __restrict__ h, const float* __restrict__ W,
                        const float* __restrict__ a) {
    extern __shared__ float Ws[];  // 128 * 132 floats; Ws[k*132 + j] = W[j*F + k]
    for (int idx = threadIdx.x; idx < F * F; idx += blockDim.x) {
        int j = idx >> 7;
        int k = idx & 127;
        Ws[k * 132 + j] = W[idx];
    }
    __syncthreads();

    const int lane = threadIdx.x & 31;
    const int wid  = threadIdx.x >> 5;
    const int wpb  = blockDim.x >> 5;
    int q = blockIdx.x * wpb + wid;
    const int nq = NN / 4;  // 12500
    if (q >= nq) return;

    const ulonglong2* WsU = (const ulonglong2*)Ws;   // row stride 33 ulonglong2
    const float4* h40 = ((const float4*)h) + (size_t)q * 4 * 32;

    unsigned long long aLo[4] = {0, 0, 0, 0};   // packed (f0,f1)
    unsigned long long aHi[4] = {0, 0, 0, 0};   // packed (f2,f3)

#pragma unroll 4
    for (int k4 = 0; k4 < 32; k4++) {
        float4 hv0 = __ldg(h40 + k4);
        float4 hv1 = __ldg(h40 + 32 + k4);
        float4 hv2 = __ldg(h40 + 64 + k4);
        float4 hv3 = __ldg(h40 + 96 + k4);
#pragma unroll
        for (int kk = 0; kk < 4; kk++) {
            ulonglong2 wv = WsU[(k4 * 4 + kk) * 33 + lane];
            unsigned long long b0 = pack2(((const float*)&hv0)[kk]);
            unsigned long long b1 = pack2(((const float*)&hv1)[kk]);
            unsigned long long b2 = pack2(((const float*)&hv2)[kk]);
            unsigned long long b3 = pack2(((const float*)&hv3)[kk]);
            fma2(aLo[0], b0, wv.x); fma2(aHi[0], b0, wv.y);
            fma2(aLo[1], b1, wv.x); fma2(aHi[1], b1, wv.y);
            fma2(aLo[2], b2, wv.x); fma2(aHi[2], b2, wv.y);
            fma2(aLo[3], b3, wv.x); fma2(aHi[3], b3, wv.y);
        }
    }

    int r0 = q * 4;
    float4* Wh4 = (float4*)d_Wh;
    float4 accv[4];
#pragma unroll
    for (int t = 0; t < 4; t++) {
        float2 lo = unpack2(aLo[t]);
        float2 hi = unpack2(aHi[t]);
        accv[t] = make_float4(lo.x, lo.y, hi.x, hi.y);
        Wh4[(size_t)(r0 + t) * 32 + lane] = accv[t];
    }

    float4 av1 = __ldg(&((const float4*)a)[lane]);        // a1
    float4 av2 = __ldg(&((const float4*)a)[32 + lane]);   // a2
    float p[8];
#pragma unroll
    for (int t = 0; t < 4; t++) {
        p[t]     = accv[t].x*av1.x + accv[t].y*av1.y + accv[t].z*av1.z + accv[t].w*av1.w;
        p[t + 4] = accv[t].x*av2.x + accv[t].y*av2.y + accv[t].z*av2.z + accv[t].w*av2.w;
    }
#pragma unroll
    for (int d = 16; d; d >>= 1) {
#pragma unroll
        for (int t = 0; t < 8; t++) p[t] += __shfl_xor_sync(0xffffffffu, p[t], d);
    }
    if (lane == 0) {
        d_s1[r0 + 0] = p[0]; d_s1[r0 + 1] = p[1]; d_s1[r0 + 2] = p[2]; d_s1[r0 + 3] = p[3];
        d_s2[r0 + 0] = p[4]; d_s2[r0 + 1] = p[5]; d_s2[r0 + 2] = p[6]; d_s2[r0 + 3] = p[7];
    }
}

// ---------------- K2: per-row counts; atomic returns rank (structure only) ----------------
__global__ void k2_count(const int* __restrict__ rows) {
    int i = blockIdx.x * blockDim.x + threadIdx.x;
    if (i >= NE) return;
    int r = __ldg(&rows[i]);
    d_rank[i] = atomicAdd(&d_cnt[r], 1);
}

// ---------------- K3a: block-level exclusive scan of counts; zero cnt ----------------
__global__ void k3a_scan() {
    int tid = threadIdx.x, lane = tid & 31, wid = tid >> 5;
    int i = blockIdx.x * 1024 + tid;
    int v = (i < NN) ? d_cnt[i] : 0;
    if (i < NN) d_cnt[i] = 0;   // restore invariant for next replay

    int incl = v;
#pragma unroll
    for (int d = 1; d < 32; d <<= 1) {
        int t = __shfl_up_sync(0xffffffffu, incl, d);
        if (lane >= d) incl += t;
    }
    __shared__ int ws[32];
    if (lane == 31) ws[wid] = incl;
    __syncthreads();
    if (wid == 0) {
        int wv = ws[lane];
        int wincl = wv;
#pragma unroll
        for (int d = 1; d < 32; d <<= 1) {
            int t = __shfl_up_sync(0xffffffffu, wincl, d);
            if (lane >= d) wincl += t;
        }
        ws[lane] = wincl - wv;
    }
    __syncthreads();
    int excl = ws[wid] + incl - v;
    if (i <= NN) d_off[i] = excl;
    if (tid == 1023) d_bsum[blockIdx.x] = excl + v;
}

// ---------------- K3b: scan of 49 block sums ----------------
__global__ void k3b_scan() {
    int t = threadIdx.x, lane = t & 31, w = t >> 5;
    int v = (t < NBLK3) ? d_bsum[t] : 0;
    int incl = v;
#pragma unroll
    for (int d = 1; d < 32; d <<= 1) {
        int x = __shfl_up_sync(0xffffffffu, incl, d);
        if (lane >= d) incl += x;
    }
    __shared__ int s0;
    if (t == 31) s0 = incl;
    __syncthreads();
    int excl = incl - v + (w ? s0 : 0);
    if (t < NBLK3) d_bpre[t] = excl;
}

// ---------------- K3c: add block offsets ----------------
__global__ void k3c_add() {
    int i = blockIdx.x * blockDim.x + threadIdx.x;
    if (i <= NN) d_off[i] += d_bpre[i >> 10];
}

// ---------------- K4: scatter cols into CSR order (no atomics) ----------------
__global__ void k4_scatter(const int* __restrict__ rows, const int* __restrict__ cols) {
    int i = blockIdx.x * blockDim.x + threadIdx.x;
    if (i >= NE) return;
    int r = __ldg(&rows[i]);
    d_ecol[d_off[r] + d_rank[i]] = __ldg(&cols[i]);
}

// ---------------- K5: per-row softmax + aggregation + elu (one warp per row) ----------------
// Coalesced chunk load of cols; per-lane s2 gather + exp; shuffle-distributed
// addresses -> all Wh gathers in a chunk are independent (MLP ~= degree).
__global__ void k5_agg(float* __restrict__ out) {
    int r    = blockIdx.x * (blockDim.x >> 5) + (threadIdx.x >> 5);
    int lane = threadIdx.x & 31;
    if (r >= NN) return;
    int s = d_off[r], e = d_off[r + 1];
    float s1r = d_s1[r];
    float4 acc = make_float4(0.f, 0.f, 0.f, 0.f);
    float sum = 0.f;
    const float4* Wh4 = (const float4*)d_Wh;

    for (int base = s; base < e; base += 32) {
        int n = e - base; if (n > 32) n = 32;
        int   cl = 0;
        float ex = 0.f;
        if (lane < n) {
            cl = d_ecol[base + lane];
            float sv = s1r + __ldg(&d_s2[cl]);
            float ev = sv > 0.f ? sv : NEG_SLOPE * sv;
            ex = __expf(ev);
        }
#pragma unroll 4
        for (int t = 0; t < n; t++) {
            int   c  = __shfl_sync(0xffffffffu, cl, t);
            float av = __shfl_sync(0xffffffffu, ex, t);
            sum += av;
            float4 w = Wh4[(size_t)c * 32 + lane];
            acc.x = fmaf(av, w.x, acc.x); acc.y = fmaf(av, w.y, acc.y);
            acc.z = fmaf(av, w.z, acc.z); acc.w = fmaf(av, w.w, acc.w);
        }
    }

    float inv = 1.f / (sum + EPSV);
    acc.x *= inv; acc.y *= inv; acc.z *= inv; acc.w *= inv;
    acc.x = acc.x > 0.f ? acc.x : expm1f(acc.x);
    acc.y = acc.y > 0.f ? acc.y : expm1f(acc.y);
    acc.z = acc.z > 0.f ? acc.z : expm1f(acc.z);
    acc.w = acc.w > 0.f ? acc.w : expm1f(acc.w);
    ((float4*)out)[(size_t)r * 32 + lane] = acc;
}

// ---------------- launch ----------------
extern "C" void kernel_launch(void* const* d_in, const int* in_sizes, int n_in,
                              void* d_out, int out_size) {
    const float* h  = (const float*)d_in[0];
    const int*   ei = (const int*)d_in[1];
    const float* W  = (const float*)d_in[2];
    const float* a  = (const float*)d_in[3];
    const int* rows = ei;
    const int* cols = ei + NE;
    float* out = (float*)d_out;

    // Lazily-created side stream + events (host resources, created once on the
    // non-captured correctness call; reused identically on every call).
    static cudaStream_t s2 = nullptr;
    static cudaEvent_t evFork = nullptr, evJoin = nullptr;
    if (s2 == nullptr) {
        cudaStreamCreateWithFlags(&s2, cudaStreamNonBlocking);
        cudaEventCreateWithFlags(&evFork, cudaEventDisableTiming);
        cudaEventCreateWithFlags(&evJoin, cudaEventDisableTiming);
    }

    cudaFuncSetAttribute(k1_gemm, cudaFuncAttributeMaxDynamicSharedMemorySize, 128 * 132 * 4);

    // Fork: CSR build (structure only) runs concurrently with the GEMM.
    cudaEventRecord(evFork, 0);
    cudaStreamWaitEvent(s2, evFork, 0);

    k1_gemm<<<(NN / 4 + 7) / 8, 256, 128 * 132 * 4>>>(h, W, a);   // main stream

    k2_count<<<(NE + 255) / 256, 256, 0, s2>>>(rows);
    k3a_scan<<<NBLK3, 1024, 0, s2>>>();
    k3b_scan<<<1, 64, 0, s2>>>();
    k3c_add<<<(NN + 256) / 256, 256, 0, s2>>>();
    k4_scatter<<<(NE + 255) / 256, 256, 0, s2>>>(rows, cols);
    cudaEventRecord(evJoin, s2);

    // Join: k5 needs Wh/s1/s2 (main) + CSR (s2).
    cudaStreamWaitEvent(0, evJoin, 0);
    k5_agg<<<(NN + 7) / 8, 256>>>(out);
}

// round 10
// speedup vs baseline: 2.0110x; 1.2018x over previous
#include <cuda_runtime.h>
#include <math.h>

#define NN 50000
#define NE 800000
#define F  128
#define NEG_SLOPE 0.2f
#define EPSV 1e-10f

#define NBLK3 49   // ceil(50000/1024)

// ---------------- scratch (device globals; no allocation) ----------------
__device__ __align__(16) float d_Wh[NN * F];     // 25.6 MB
__device__ float d_s1[NN];
__device__ float d_s2[NN];
__device__ int   d_rank[NE];                     // rank of edge within its row
__device__ int   d_cnt[NN];                      // zero-initialized; re-zeroed by k3
__device__ int   d_off[NN + 1];
__device__ int   d_bagg[NBLK3];
__device__ int   d_bflag[NBLK3];                 // zeroed by k2 each run
__device__ int   d_ecol[NE];                     // cols in CSR order

// ---------------- packed f32x2 helpers (sm_103a) ----------------
__device__ __forceinline__ void fma2(unsigned long long& d, unsigned long long a,
                                     unsigned long long b) {
    asm("fma.rn.f32x2 %0, %1, %2, %0;" : "+l"(d) : "l"(a), "l"(b));
}
__device__ __forceinline__ unsigned long long pack2(float x) {
    unsigned long long r;
    asm("mov.b64 %0, {%1, %1};" : "=l"(r) : "f"(x));
    return r;
}
__device__ __forceinline__ float2 unpack2(unsigned long long v) {
    float lo, hi;
    asm("mov.b64 {%0, %1}, %2;" : "=f"(lo), "=f"(hi) : "l"(v));
    return make_float2(lo, hi);
}

// ---------------- K1: Wh = h @ W^T (packed f32x2), fused s1/s2 ----------------
// 8 rows per warp (halves shared-W traffic per FMA); lane owns 4 output features.
__global__ void __launch_bounds__(256) k1_gemm(const float* __restrict__ h,
                                               const float* __restrict__ W,
                                               const float* __restrict__ a) {
    extern __shared__ float Ws[];  // 128 * 132 floats; Ws[k*132 + j] = W[j*F + k]
    for (int idx = threadIdx.x; idx < F * F; idx += blockDim.x) {
        int j = idx >> 7;
        int k = idx & 127;
        Ws[k * 132 + j] = W[idx];
    }
    __syncthreads();

    const int lane = threadIdx.x & 31;
    const int wid  = threadIdx.x >> 5;
    int q = blockIdx.x * (blockDim.x >> 5) + wid;   // warp id, 8 rows each
    const int nq = NN / 8;  // 6250
    if (q >= nq) return;

    const ulonglong2* WsU = (const ulonglong2*)Ws;   // row stride 33 ulonglong2
    const float4* h40 = ((const float4*)h) + (size_t)q * 8 * 32;

    unsigned long long aLo[8] = {0,0,0,0,0,0,0,0};
    unsigned long long aHi[8] = {0,0,0,0,0,0,0,0};

#pragma unroll 2
    for (int k4 = 0; k4 < 32; k4++) {
        float4 hv[8];
#pragma unroll
        for (int t = 0; t < 8; t++) hv[t] = __ldg(h40 + t * 32 + k4);
#pragma unroll
        for (int kk = 0; kk < 4; kk++) {
            ulonglong2 wv = WsU[(k4 * 4 + kk) * 33 + lane];
#pragma unroll
            for (int t = 0; t < 8; t++) {
                unsigned long long b = pack2(((const float*)&hv[t])[kk]);
                fma2(aLo[t], b, wv.x);
                fma2(aHi[t], b, wv.y);
            }
        }
    }

    int r0 = q * 8;
    float4* Wh4 = (float4*)d_Wh;
    float4 av1 = __ldg(&((const float4*)a)[lane]);        // a1
    float4 av2 = __ldg(&((const float4*)a)[32 + lane]);   // a2
    float p1[8], p2[8];
#pragma unroll
    for (int t = 0; t < 8; t++) {
        float2 lo = unpack2(aLo[t]);
        float2 hi = unpack2(aHi[t]);
        float4 v = make_float4(lo.x, lo.y, hi.x, hi.y);
        Wh4[(size_t)(r0 + t) * 32 + lane] = v;
        p1[t] = v.x*av1.x + v.y*av1.y + v.z*av1.z + v.w*av1.w;
        p2[t] = v.x*av2.x + v.y*av2.y + v.z*av2.z + v.w*av2.w;
    }
#pragma unroll
    for (int d = 16; d; d >>= 1) {
#pragma unroll
        for (int t = 0; t < 8; t++) {
            p1[t] += __shfl_xor_sync(0xffffffffu, p1[t], d);
            p2[t] += __shfl_xor_sync(0xffffffffu, p2[t], d);
        }
    }
    if (lane == 0) {
#pragma unroll
        for (int t = 0; t < 8; t++) {
            d_s1[r0 + t] = p1[t];
            d_s2[r0 + t] = p2[t];
        }
    }
}

// ---------------- K2: per-row counts; atomic returns rank; zero scan flags ----------------
__global__ void k2_count(const int* __restrict__ rows) {
    int i = blockIdx.x * blockDim.x + threadIdx.x;
    if (i < NBLK3) d_bflag[i] = 0;   // reset lookback flags for this replay
    if (i >= NE) return;
    int r = __ldg(&rows[i]);
    d_rank[i] = atomicAdd(&d_cnt[r], 1);
}

// ---------------- K3: single-kernel exclusive scan (parallel lookback) ----------------
// 49 blocks x 1024, all co-resident (< 148 SMs) -> spin-wait is deadlock-free.
__global__ void __launch_bounds__(1024) k3_scan() {
    int tid = threadIdx.x, lane = tid & 31, wid = tid >> 5;
    int b = blockIdx.x;
    int i = b * 1024 + tid;
    int v = (i < NN) ? d_cnt[i] : 0;
    if (i < NN) d_cnt[i] = 0;   // restore invariant for next replay

    // block-level exclusive scan
    int incl = v;
#pragma unroll
    for (int d = 1; d < 32; d <<= 1) {
        int t = __shfl_up_sync(0xffffffffu, incl, d);
        if (lane >= d) incl += t;
    }
    __shared__ int ws[32];
    __shared__ int s_pref;
    if (lane == 31) ws[wid] = incl;
    __syncthreads();
    if (wid == 0) {
        int wv = ws[lane];
        int wincl = wv;
#pragma unroll
        for (int d = 1; d < 32; d <<= 1) {
            int t = __shfl_up_sync(0xffffffffu, wincl, d);
            if (lane >= d) wincl += t;
        }
        ws[lane] = wincl - wv;
    }
    __syncthreads();
    int excl = ws[wid] + incl - v;

    // publish this block's aggregate
    if (tid == 1023) {
        d_bagg[b] = excl + v;
        __threadfence();
        atomicExch(&d_bflag[b], 1);
    }

    // warp 0: gather all predecessor aggregates in parallel lanes
    if (wid == 0) {
        int p = 0;
        for (int j = lane; j < b; j += 32) {
            while (atomicAdd(&d_bflag[j], 0) == 0) { }
            p += d_bagg[j];
        }
#pragma unroll
        for (int d = 16; d; d >>= 1) p += __shfl_xor_sync(0xffffffffu, p, d);
        if (lane == 0) s_pref = p;
    }
    __syncthreads();
    if (i <= NN) d_off[i] = s_pref + excl;
}

// ---------------- K4: scatter cols into CSR order (no atomics) ----------------
__global__ void k4_scatter(const int* __restrict__ rows, const int* __restrict__ cols) {
    int i = blockIdx.x * blockDim.x + threadIdx.x;
    if (i >= NE) return;
    int r = __ldg(&rows[i]);
    d_ecol[d_off[r] + d_rank[i]] = __ldg(&cols[i]);
}

// ---------------- K5: per-row softmax + aggregation + elu (one warp per row) ----------------
__global__ void k5_agg(float* __restrict__ out) {
    int r    = blockIdx.x * (blockDim.x >> 5) + (threadIdx.x >> 5);
    int lane = threadIdx.x & 31;
    if (r >= NN) return;
    int s = d_off[r], e = d_off[r + 1];
    float s1r = d_s1[r];
    float4 acc = make_float4(0.f, 0.f, 0.f, 0.f);
    float sum = 0.f;
    const float4* Wh4 = (const float4*)d_Wh;

    for (int base = s; base < e; base += 32) {
        int n = e - base; if (n > 32) n = 32;
        int   cl = 0;
        float ex = 0.f;
        if (lane < n) {
            cl = d_ecol[base + lane];
            float sv = s1r + __ldg(&d_s2[cl]);
            float ev = sv > 0.f ? sv : NEG_SLOPE * sv;
            ex = __expf(ev);
        }
#pragma unroll 4
        for (int t = 0; t < n; t++) {
            int   c  = __shfl_sync(0xffffffffu, cl, t);
            float av = __shfl_sync(0xffffffffu, ex, t);
            sum += av;
            float4 w = Wh4[(size_t)c * 32 + lane];
            acc.x = fmaf(av, w.x, acc.x); acc.y = fmaf(av, w.y, acc.y);
            acc.z = fmaf(av, w.z, acc.z); acc.w = fmaf(av, w.w, acc.w);
        }
    }

    float inv = 1.f / (sum + EPSV);
    acc.x *= inv; acc.y *= inv; acc.z *= inv; acc.w *= inv;
    acc.x = acc.x > 0.f ? acc.x : expm1f(acc.x);
    acc.y = acc.y > 0.f ? acc.y : expm1f(acc.y);
    acc.z = acc.z > 0.f ? acc.z : expm1f(acc.z);
    acc.w = acc.w > 0.f ? acc.w : expm1f(acc.w);
    ((float4*)out)[(size_t)r * 32 + lane] = acc;
}

// ---------------- launch ----------------
extern "C" void kernel_launch(void* const* d_in, const int* in_sizes, int n_in,
                              void* d_out, int out_size) {
    const float* h  = (const float*)d_in[0];
    const int*   ei = (const int*)d_in[1];
    const float* W  = (const float*)d_in[2];
    const float* a  = (const float*)d_in[3];
    const int* rows = ei;
    const int* cols = ei + NE;
    float* out = (float*)d_out;

    static cudaStream_t s2 = nullptr;
    static cudaEvent_t evFork = nullptr, evJoin = nullptr;
    if (s2 == nullptr) {
        cudaStreamCreateWithFlags(&s2, cudaStreamNonBlocking);
        cudaEventCreateWithFlags(&evFork, cudaEventDisableTiming);
        cudaEventCreateWithFlags(&evJoin, cudaEventDisableTiming);
    }

    cudaFuncSetAttribute(k1_gemm, cudaFuncAttributeMaxDynamicSharedMemorySize, 128 * 132 * 4);

    // Fork: CSR build (structure only) runs concurrently with the GEMM.
    cudaEventRecord(evFork, 0);
    cudaStreamWaitEvent(s2, evFork, 0);

    k1_gemm<<<(NN / 8 + 7) / 8, 256, 128 * 132 * 4>>>(h, W, a);   // main stream

    k2_count<<<(NE + 255) / 256, 256, 0, s2>>>(rows);
    k3_scan<<<NBLK3, 1024, 0, s2>>>();
    k4_scatter<<<(NE + 255) / 256, 256, 0, s2>>>(rows, cols);
    cudaEventRecord(evJoin, s2);

    // Join: k5 needs Wh/s1/s2 (main) + CSR (s2).
    cudaStreamWaitEvent(0, evJoin, 0);
    k5_agg<<<(NN + 7) / 8, 256>>>(out);
}